// round 1
// baseline (speedup 1.0000x reference)
#include <cuda_runtime.h>
#include <cstdint>
#include <cstddef>

// ----------------------------------------------------------------------------
// InstanceSegmentationHead: level assignment + per-level greedy NMS (K=64)
// + ROI align (14x14, 2x2 samples) over 3 feature levels.
// Shapes fixed by the problem: B=2, C=256, N=2048 per source, levels 28/56/112.
// ----------------------------------------------------------------------------

#define NBOX 6144
#define NEGV (-1e30f)
#define BATCH 2
#define CCH 256
#define KKEEP 64
#define OUTP 14

// ---------------- scratch (__device__ globals; no allocation) ---------------
__device__ unsigned long long g_ckey[6][NBOX];   // packed (ordered_score<<32 | ~orig_idx)
__device__ float4             g_cbox[6][NBOX];   // compacted xyxy (scaled)
__device__ int                g_cnt[6];
__device__ int                g_sel[6][KKEEP];
__device__ float4             g_scaled[BATCH][NBOX]; // cx,cy,w,h (scaled)

// order-preserving float->uint mapping (monotonic: a<b  <=>  ford(a)<ford(b))
__device__ __forceinline__ unsigned ford(float f) {
    unsigned u = __float_as_uint(f);
    return (u & 0x80000000u) ? ~u : (u | 0x80000000u);
}

// ---------------------------- stage 0: zero counters -------------------------
__global__ void zero_kernel() {
    if (threadIdx.x < 6) g_cnt[threadIdx.x] = 0;
}

// ------------------- stage 1: prep boxes, levels, compaction -----------------
__global__ void prep_kernel(const float* __restrict__ b32, const float* __restrict__ b16,
                            const float* __restrict__ b8,
                            const float* __restrict__ s32, const float* __restrict__ s16,
                            const float* __restrict__ s8) {
    int i = blockIdx.x * blockDim.x + threadIdx.x;
    if (i >= BATCH * NBOX) return;
    int b = i / NBOX;
    int j = i - b * NBOX;

    const float* bp;
    const float* sp;
    float sc;
    if (j < 2048)      { bp = b32 + ((size_t)b * 2048 + j) * 4;          sp = s32 + (size_t)b * 2048 + j;          sc = 32.f; }
    else if (j < 4096) { int jj = j - 2048; bp = b16 + ((size_t)b * 2048 + jj) * 4; sp = s16 + (size_t)b * 2048 + jj; sc = 16.f; }
    else               { int jj = j - 4096; bp = b8  + ((size_t)b * 2048 + jj) * 4; sp = s8  + (size_t)b * 2048 + jj; sc = 8.f;  }

    float cx = bp[0], cy = bp[1], w = bp[2], h = bp[3];

    // level from UNscaled size: clip(floor(3 + log2(sqrt(w*h)/224)), 1, 4)
    float s  = sqrtf(__fmul_rn(w, h));
    float lv = floorf(__fadd_rn(3.0f, log2f(__fdiv_rn(s, 224.0f))));
    lv = fminf(fmaxf(lv, 1.0f), 4.0f);

    // scaled cxcywh and xyxy (single-op IEEE rounding; no fma contraction)
    float scx = __fmul_rn(cx, sc), scy = __fmul_rn(cy, sc);
    float sw  = __fmul_rn(w,  sc), sh  = __fmul_rn(h,  sc);
    g_scaled[b][j] = make_float4(scx, scy, sw, sh);
    float hx = __fmul_rn(sw, 0.5f), hy = __fmul_rn(sh, 0.5f);
    float x1 = __fsub_rn(scx, hx), y1 = __fsub_rn(scy, hy);
    float x2 = __fadd_rn(scx, hx), y2 = __fadd_rn(scy, hy);

    int lvl = (int)lv;
    if (lvl >= 1 && lvl <= 3) {
        int bl  = b * 3 + (lvl - 1);
        int pos = atomicAdd(&g_cnt[bl], 1);
        g_cbox[bl][pos] = make_float4(x1, y1, x2, y2);
        // key: higher score wins; ties -> smaller original index wins (matches jnp.argmax)
        unsigned long long key =
            ((unsigned long long)ford(*sp) << 32) |
            (unsigned long long)(0xFFFFFFFFu - (unsigned)j);
        g_ckey[bl][pos] = key;
    }
}

// --------------------------- stage 2: greedy NMS -----------------------------
// one block per (batch, level); serial 64-iteration argmax+suppress in SMEM
__global__ void nms_kernel() {
    extern __shared__ char smraw[];
    unsigned long long* skey = (unsigned long long*)smraw;
    float4* sbox = (float4*)(smraw + (size_t)NBOX * sizeof(unsigned long long));

    __shared__ unsigned long long rk[16];
    __shared__ int                rp[16];
    __shared__ unsigned long long wkey_s;
    __shared__ int                wpos_s;

    const int BD  = 512;
    int bl  = blockIdx.x;
    int n   = g_cnt[bl];
    int tid = threadIdx.x;

    for (int j = tid; j < n; j += BD) {
        skey[j] = g_ckey[bl][j];
        sbox[j] = g_cbox[bl][j];
    }
    __syncthreads();

    const unsigned long long KTHRESH = ((unsigned long long)ford(-5e29f)) << 32; // NEG/2
    const unsigned FNEG = ford(NEGV);

    int it = 0;
    for (; it < KKEEP; ++it) {
        // block argmax over packed keys
        unsigned long long bk = 0ull;
        int bp = 0;
        for (int j = tid; j < n; j += BD) {
            unsigned long long k = skey[j];
            if (k > bk) { bk = k; bp = j; }
        }
        #pragma unroll
        for (int off = 16; off; off >>= 1) {
            unsigned long long ok = __shfl_down_sync(0xFFFFFFFFu, bk, off);
            int                op = __shfl_down_sync(0xFFFFFFFFu, bp, off);
            if (ok > bk) { bk = ok; bp = op; }
        }
        if ((tid & 31) == 0) { rk[tid >> 5] = bk; rp[tid >> 5] = bp; }
        __syncthreads();
        if (tid < 32) {
            bk = (tid < 16) ? rk[tid] : 0ull;
            bp = (tid < 16) ? rp[tid] : 0;
            #pragma unroll
            for (int off = 8; off; off >>= 1) {
                unsigned long long ok = __shfl_down_sync(0xFFFFFFFFu, bk, off);
                int                op = __shfl_down_sync(0xFFFFFFFFu, bp, off);
                if (ok > bk) { bk = ok; bp = op; }
            }
            if (tid == 0) { wkey_s = bk; wpos_s = bp; }
        }
        __syncthreads();

        unsigned long long wk = wkey_s;
        if (wk <= KTHRESH) break;  // best score <= NEG/2 -> remaining sel = -1

        int wp = wpos_s;
        if (tid == 0)
            g_sel[bl][it] = (int)(0xFFFFFFFFu - (unsigned)(wk & 0xFFFFFFFFull));

        float4 bx = sbox[wp];
        float a = __fmul_rn(fmaxf(__fsub_rn(bx.z, bx.x), 0.f),
                            fmaxf(__fsub_rn(bx.w, bx.y), 0.f));

        for (int j = tid; j < n; j += BD) {
            float4 bb = sbox[j];
            float ix1 = fmaxf(bx.x, bb.x), iy1 = fmaxf(bx.y, bb.y);
            float ix2 = fminf(bx.z, bb.z), iy2 = fminf(bx.w, bb.w);
            float inter = __fmul_rn(fmaxf(__fsub_rn(ix2, ix1), 0.f),
                                    fmaxf(__fsub_rn(iy2, iy1), 0.f));
            float ab = __fmul_rn(fmaxf(__fsub_rn(bb.z, bb.x), 0.f),
                                 fmaxf(__fsub_rn(bb.w, bb.y), 0.f));
            float denom = __fadd_rn(__fsub_rn(__fadd_rn(a, ab), inter), 1e-9f);
            float iou   = __fdiv_rn(inter, denom);
            if (iou > 0.7f)
                skey[j] = (((unsigned long long)FNEG) << 32) | (skey[j] & 0xFFFFFFFFull);
        }
        __syncthreads();
    }

    for (int j = it + tid; j < KKEEP; j += BD) g_sel[bl][j] = -1;
}

// ---------------------------- stage 3: ROI align -----------------------------
// grid.x = B*192 (one (b,k) per x), grid.y = 8 channel groups of 32
__global__ void roi_kernel(const float* __restrict__ p32,
                           const float* __restrict__ p16,
                           const float* __restrict__ p8,
                           float* __restrict__ out) {
    int bk  = blockIdx.x;          // 0..383
    int b   = bk / 192;
    int k   = bk - b * 192;
    int lvl = k / KKEEP;           // 0,1,2
    int kk  = k - lvl * KKEEP;
    int cg  = blockIdx.y * 32;     // channel group base

    float* o = out + ((size_t)(b * 192 + k)) * (CCH * OUTP * OUTP)
                   + (size_t)cg * (OUTP * OUTP);

    int sel = g_sel[b * 3 + lvl][kk];
    const int NLOC = 32 * OUTP * OUTP;   // 6272 elems per block
    if (sel < 0) {
        for (int i = threadIdx.x; i < NLOC; i += blockDim.x) o[i] = 0.0f;
        return;
    }

    int S = (lvl == 0) ? 28 : (lvl == 1) ? 56 : 112;
    const float* fbase = ((lvl == 0) ? p32 : (lvl == 1) ? p16 : p8)
                         + ((size_t)b * CCH + cg) * (size_t)S * S;

    // NOTE: reference feeds scaled cx,cy,w,h into roi_align as x1,y1,x2,y2
    float4 box = g_scaled[b][sel];
    float x1 = box.x, y1 = box.y, x2 = box.z, y2 = box.w;
    float bw = __fdiv_rn(__fsub_rn(x2, x1), 14.0f);
    float bh = __fdiv_rn(__fsub_rn(y2, y1), 14.0f);

    __shared__ int   sx0[28], sx1[28], sy0[28], sy1[28];
    __shared__ float sfx[28], sfy[28];
    if (threadIdx.x < 28) {
        int j = threadIdx.x;
        float t = __fadd_rn((float)(j >> 1), (j & 1) ? 0.75f : 0.25f);
        float lim = (float)(S - 1);

        float cx = __fadd_rn(x1, __fmul_rn(t, bw));
        cx = fminf(fmaxf(cx, 0.0f), lim);
        float cx0 = floorf(cx);
        sfx[j] = __fsub_rn(cx, cx0);
        int ix0 = (int)cx0;
        sx0[j] = ix0;
        sx1[j] = min(ix0 + 1, S - 1);

        float cy = __fadd_rn(y1, __fmul_rn(t, bh));
        cy = fminf(fmaxf(cy, 0.0f), lim);
        float cy0 = floorf(cy);
        sfy[j] = __fsub_rn(cy, cy0);
        int iy0 = (int)cy0;
        sy0[j] = iy0;
        sy1[j] = min(iy0 + 1, S - 1);
    }
    __syncthreads();

    for (int i = threadIdx.x; i < NLOC; i += blockDim.x) {
        int c  = i / (OUTP * OUTP);
        int p  = i - c * (OUTP * OUTP);
        int oy = p / OUTP;
        int ox = p - oy * OUTP;
        const float* f = fbase + (size_t)c * S * S;

        float acc = 0.0f;
        #pragma unroll
        for (int sy = 0; sy < 2; ++sy) {
            int yi  = 2 * oy + sy;
            int Y0  = sy0[yi] * S;
            int Y1  = sy1[yi] * S;
            float fy  = sfy[yi];
            float ify = 1.0f - fy;
            #pragma unroll
            for (int sx = 0; sx < 2; ++sx) {
                int xi  = 2 * ox + sx;
                int X0  = sx0[xi];
                int X1  = sx1[xi];
                float fx  = sfx[xi];
                float ifx = 1.0f - fx;
                float g00 = __ldg(f + Y0 + X0);
                float g01 = __ldg(f + Y0 + X1);
                float g10 = __ldg(f + Y1 + X0);
                float g11 = __ldg(f + Y1 + X1);
                acc += g00 * (ify * ifx) + g01 * (ify * fx)
                     + g10 * (fy * ifx) + g11 * (fy * fx);
            }
        }
        o[i] = acc * 0.25f;
    }
}

// ------------------------------- launcher ------------------------------------
extern "C" void kernel_launch(void* const* d_in, const int* in_sizes, int n_in,
                              void* d_out, int out_size) {
    const float* p32 = (const float*)d_in[0];
    const float* p16 = (const float*)d_in[1];
    const float* p8  = (const float*)d_in[2];
    // d_in[3] = p4 (unused by the reference forward)
    const float* b32 = (const float*)d_in[4];
    const float* b16 = (const float*)d_in[5];
    const float* b8  = (const float*)d_in[6];
    const float* s32 = (const float*)d_in[7];
    const float* s16 = (const float*)d_in[8];
    const float* s8  = (const float*)d_in[9];
    float* out = (float*)d_out;

    // NMS block needs 147456 B dynamic smem (keys 48K + boxes 96K): opt in.
    static const size_t NMS_SMEM =
        (size_t)NBOX * sizeof(unsigned long long) + (size_t)NBOX * sizeof(float4);
    cudaFuncSetAttribute(nms_kernel, cudaFuncAttributeMaxDynamicSharedMemorySize,
                         (int)NMS_SMEM);

    zero_kernel<<<1, 32>>>();
    prep_kernel<<<(BATCH * NBOX + 255) / 256, 256>>>(b32, b16, b8, s32, s16, s8);
    nms_kernel<<<6, 512, NMS_SMEM>>>();

    dim3 rg(BATCH * 192, 8);
    roi_kernel<<<rg, 256>>>(p32, p16, p8, out);
}